// round 13
// baseline (speedup 1.0000x reference)
#include <cuda_runtime.h>
#include <cstdint>

#define VOCAB 100000
#define EMBED 128

// 51.2 MB transposed (+bias-fused) weight scratch: g_Wt[v][e] = W[e][v] + b[e]
// 32B alignment required for v8.f32 accesses.
__device__ __align__(32) float g_Wt[(size_t)VOCAB * EMBED];
// index-dtype flag: 1 = int64 indices, 0 = int32 indices
__device__ int g_is64;

// ---- 256-bit L2 eviction-policy accessors (sm_103 requires .v8.f32) -------
__device__ __forceinline__ void ldg8_evict_last(const float* p, float* v) {
    asm volatile(
        "ld.global.nc.L2::evict_last.v8.f32 {%0,%1,%2,%3,%4,%5,%6,%7}, [%8];"
        : "=f"(v[0]), "=f"(v[1]), "=f"(v[2]), "=f"(v[3]),
          "=f"(v[4]), "=f"(v[5]), "=f"(v[6]), "=f"(v[7])
        : "l"(p));
}
__device__ __forceinline__ void stg8_evict_first(float* p, const float* v) {
    asm volatile(
        "st.global.L2::evict_first.v8.f32 [%0], {%1,%2,%3,%4,%5,%6,%7,%8};"
        :: "l"(p),
           "f"(v[0]), "f"(v[1]), "f"(v[2]), "f"(v[3]),
           "f"(v[4]), "f"(v[5]), "f"(v[6]), "f"(v[7])
        : "memory");
}

// ---------------------------------------------------------------------------
// Transpose W [EMBED=128, VOCAB] -> g_Wt [VOCAB, EMBED], fusing the bias add
// and the index-dtype detection (block 0, thread 0).
//
// One block handles a 128(e) x 32(v) tile. 256 threads.
// Load:  warp reads 32 consecutive v for fixed e  -> 128B coalesced.
// smem pad 129: s[j*129+e], lanes vary j -> banks (j+e)%32, conflict-free.
// Store: consecutive tid -> consecutive e for fixed v -> 128B coalesced,
//        smem read s[vr*129+e] lanes consecutive e -> conflict-free.
// Measured ~15us ≈ its 102MB bandwidth floor — unchanged.
// ---------------------------------------------------------------------------
__global__ __launch_bounds__(256) void transpose_kernel(
    const float* __restrict__ W,
    const float* __restrict__ bias,
    const unsigned int* __restrict__ xw)
{
    __shared__ float s[32 * 129];
    __shared__ float sb[EMBED];

    const int v0 = blockIdx.x * 32;
    const int tid = threadIdx.x;       // 0..255
    const int j = tid & 31;            // v within tile
    const int eb = tid >> 5;           // 0..7

    // dtype detection: indices < 2^31, so int64 buffers have zero odd words.
    // P(false positive on int32 data) ~ (2^-32)^8.
    if (blockIdx.x == 0 && tid == 0) {
        int is64 = 1;
#pragma unroll
        for (int i = 0; i < 8; i++)
            if (xw[2 * i + 1] != 0u) is64 = 0;
        g_is64 = is64;
    }

    if (tid < EMBED) sb[tid] = bias[tid];

#pragma unroll
    for (int k = 0; k < 16; k++) {
        int e = eb + k * 8;            // 0..127
        s[j * 129 + e] = W[(size_t)e * VOCAB + (v0 + j)];
    }
    __syncthreads();

#pragma unroll
    for (int m = 0; m < 16; m++) {
        int idx = m * 256 + tid;       // 0..4095
        int vr = idx >> 7;             // 0..31
        int e  = idx & 127;            // 0..127
        g_Wt[(size_t)(v0 + vr) * EMBED + e] = s[vr * 129 + e] + sb[e];
    }
}

// ---------------------------------------------------------------------------
// Gather, MLP=4: each 256-thread block serves 64 tokens; every thread handles
// FOUR tokens (tok = base + tid/16 + 16k), issuing all four independent v8
// loads before any store. MLP progression measured: DRAM% 68.6 (MLP=1) ->
// 75.6 (MLP=2); this targets the remaining latency exposure. Regs ~40 ->
// ~6 blocks/SM residency, similar occupancy to before but ~1.9x in-flight
// request depth per SM.
//
// Reads:  v8 + L2::evict_last  -> Wt (51.2MB) stays pinned in L2 (126MB).
// Writes: v8 + L2::evict_first -> 419MB output stream recycles a small
//         L2 slice instead of displacing Wt. Warp stores remain 1024B
//         contiguous per store instruction.
// ---------------------------------------------------------------------------
__global__ __launch_bounds__(256) void gather_kernel(
    const void* __restrict__ xraw,
    float* __restrict__ out,
    int ntok)
{
    const int tid = threadIdx.x;
    const int seg = tid & 15;                          // 32B chunk of the row
    const int tok0 = blockIdx.x * 64 + (tid >> 4);     // tokens, stride 16

    long long idx[4];
    if (g_is64) {
        const long long* xp = (const long long*)xraw;
#pragma unroll
        for (int k = 0; k < 4; k++) {
            int t = tok0 + 16 * k;
            idx[k] = (t < ntok) ? xp[t] : 0;
        }
    } else {
        const int* xp = (const int*)xraw;
#pragma unroll
        for (int k = 0; k < 4; k++) {
            int t = tok0 + 16 * k;
            idx[k] = (t < ntok) ? (long long)xp[t] : 0;
        }
    }

    float v[4][8];
    // all four independent loads in flight before any store
#pragma unroll
    for (int k = 0; k < 4; k++)
        ldg8_evict_last(g_Wt + (size_t)idx[k] * EMBED + seg * 8, v[k]);

#pragma unroll
    for (int k = 0; k < 4; k++) {
        int t = tok0 + 16 * k;
        if (t < ntok)
            stg8_evict_first(out + (size_t)t * EMBED + seg * 8, v[k]);
    }
}

// ---------------------------------------------------------------------------
// Inputs (metadata order): d_in[0] = x [4096*200] int32/int64,
//                          d_in[1] = W [128*100000] f32,
//                          d_in[2] = b [128] f32.
// Output: [4096*200*128] f32.
// ---------------------------------------------------------------------------
extern "C" void kernel_launch(void* const* d_in, const int* in_sizes, int n_in,
                              void* d_out, int out_size) {
    const void* x = d_in[0];
    const float* W = (const float*)d_in[1];
    const float* b = (const float*)d_in[2];
    float* out = (float*)d_out;
    const int ntok = in_sizes[0];  // 819200 tokens (element count, dtype-independent)

    // VOCAB = 100000 = 3125 tiles of 32 columns
    transpose_kernel<<<VOCAB / 32, 256>>>(W, b, (const unsigned int*)x);

    // 64 tokens per 256-thread block (4 tokens per thread)
    const int tok_per_block = 64;
    const int nblk = (ntok + tok_per_block - 1) / tok_per_block;
    gather_kernel<<<nblk, 256>>>(x, out, ntok);
}